// round 15
// baseline (speedup 1.0000x reference)
#include <cuda_runtime.h>
#include <math.h>

#define N_TOK 65536
#define DD 64
#define KC 1024
#define NELEM 4194304
#define OFF_LOSS 4194304
#define OFF_IDX  4194305
#define OFF_EMB  4259841
#define OFF_CS   4325377
#define OFF_EMAW 4326401

// ---------------- scratch (device globals; no allocations allowed) ----------
__device__ float  g_et[DD * KC];          // E transposed [d][k] (k-major rows)
__device__ float  g_e2[KC];
__device__ int    g_idx[N_TOK];
__device__ int    g_counts[KC];
__device__ float  g_dwf[KC * DD];
__device__ double g_mse;
__device__ float  g_newcs[KC];

typedef unsigned long long ull;
typedef unsigned int uint32;

__device__ __forceinline__ ull pk2(float lo, float hi) {
    ull r; asm("mov.b64 %0, {%1, %2};" : "=l"(r) : "f"(lo), "f"(hi)); return r;
}
__device__ __forceinline__ void upk2(ull v, float &lo, float &hi) {
    asm("mov.b64 {%0, %1}, %2;" : "=f"(lo), "=f"(hi) : "l"(v));
}
__device__ __forceinline__ ull fma2(ull a, ull b, ull c) {
    ull d; asm("fma.rn.f32x2 %0, %1, %2, %3;" : "=l"(d) : "l"(a), "l"(b), "l"(c)); return d;
}
__device__ __forceinline__ void cpa16(uint32 dst, const void* src) {
    asm volatile("cp.async.cg.shared.global [%0], [%1], 16;" :: "r"(dst), "l"(src));
}
__device__ __forceinline__ void cpa_commit() { asm volatile("cp.async.commit_group;"); }
__device__ __forceinline__ void cpa_wait0()  { asm volatile("cp.async.wait_group 0;"); }

// ---------------- kernel: zero scratch + e2 + E transpose (merged) ----------
__global__ void k_init(const float* __restrict__ E) {
    int b = blockIdx.x, t = threadIdx.x;
    if (b < 256) {
        int i = b * 256 + t;                 // 65536: covers all of g_dwf
        g_dwf[i] = 0.f;
        if (i < KC) g_counts[i] = 0;
        if (i == 0) g_mse = 0.0;
    } else {
        int k = (b - 256) * 256 + t;         // 0..1023
        const float4* e = (const float4*)(E + ((size_t)k << 6));
        float s = 0.f;
#pragma unroll
        for (int q = 0; q < 16; q++) {
            float4 v = e[q];
            int d = q << 2;
            g_et[(d + 0) * KC + k] = v.x;    // coalesced over k
            g_et[(d + 1) * KC + k] = v.y;
            g_et[(d + 2) * KC + k] = v.z;
            g_et[(d + 3) * KC + k] = v.w;
            s = __fadd_rn(s, __fmul_rn(v.x, v.x));
            s = __fadd_rn(s, __fmul_rn(v.y, v.y));
            s = __fadd_rn(s, __fmul_rn(v.z, v.z));
            s = __fadd_rn(s, __fmul_rn(v.w, v.w));
        }
        g_e2[k] = s;
    }
}

// ---------------- kernel: fused rotation + distance GEMM + argmin + stats ---
#define GEMM_SMEM (32768 * 3 + 4096 + 512 + 512)
__global__ void __launch_bounds__(256, 2) k_gemm(const float* __restrict__ E,
                                                 const float* __restrict__ X,
                                                 const float* __restrict__ Rg,
                                                 float* __restrict__ out_idx_f) {
    extern __shared__ char sm[];
    float* xs   = (float*)sm;                        // [64][128] k-major x_rot
    float* esb0 = (float*)(sm + 32768);              // [64][128]
    float* esb1 = (float*)(sm + 65536);
    float* se2  = (float*)(sm + 98304);              // [1024]
    float* sx2  = (float*)(sm + 102400);             // [128]
    int*   sidx = (int*)(sm + 102912);               // [128]
    // prologue overlays (dead before es buffers are loaded):
    float* xsraw = esb0;                             // [64 c][128 tok] raw X
    float* Rs    = esb1;                             // [64][64]
    float* sp    = (float*)(sm + 65536 + 16384);     // [4][128] x2 partials
    float* redd = esb0;                              // overlay after loop
    int*   redj = (int*)(sm + 32768 + 8192);

    int t = threadIdx.x;
    int lane = t & 31, w = t >> 5;
    int rr = ((w >> 1) << 2) | (lane >> 3);
    int cr = ((w & 1) << 3) | (lane & 7);
    int m0 = blockIdx.x << 7;

    uint32 es_u[2] = { (uint32)__cvta_generic_to_shared(esb0),
                       (uint32)__cvta_generic_to_shared(esb1) };
    uint32 se2_u  = (uint32)__cvta_generic_to_shared(se2);

    // ---- phase 0: async-load X block rows (32KB), R (16KB), e2 (4KB) ----
    {
        const float* Xblk = X + ((size_t)(m0 >> 12) << 18) + (m0 & 4095);
#pragma unroll
        for (int q = 0; q < 8; q++) {                // xsraw: 2048 x 16B = 32KB
            int lin = (q << 8) + t;
            int row = lin >> 5, seg = lin & 31;
            cpa16(es_u[0] + (((row << 7) + (seg << 2)) << 2),
                  Xblk + (size_t)row * 4096 + (seg << 2));
        }
#pragma unroll
        for (int q = 0; q < 4; q++) {                // Rs: 1024 x 16B = 16KB
            int lin = (q << 8) + t;
            cpa16(es_u[1] + (lin << 4), Rg + (lin << 2));
        }
        cpa16(se2_u + (t << 4), g_e2 + (t << 2));    // se2: 256 x 16B = 4KB
        cpa_commit();
        cpa_wait0();
        __syncthreads();
    }

    // ---- phase 1: rotate 128 tokens (bit-exact vs old k_rotate) ----
    {
        int tok = t & 127, half = t >> 7;            // half: dims [32h, 32h+32)
        ull r2[16];
#pragma unroll
        for (int i = 0; i < 16; i++) r2[i] = 0ull;
        const ull* R2base = (const ull*)(Rs + (half << 5));
#pragma unroll 8
        for (int c = 0; c < 64; c++) {               // ascending c, fma chains
            float xv = xsraw[(c << 7) + tok];
            ull xd = pk2(xv, xv);
            const ull* Rrow = R2base + (c << 5);
#pragma unroll
            for (int i = 0; i < 16; i++)
                r2[i] = fma2(xd, Rrow[i], r2[i]);
        }
        float rv[32];
#pragma unroll
        for (int i = 0; i < 16; i++) upk2(r2[i], rv[2 * i], rv[2 * i + 1]);
        float s0 = 0.f, s1 = 0.f;
#pragma unroll
        for (int i = 0; i < 16; i++) s0 = __fadd_rn(s0, __fmul_rn(rv[i], rv[i]));
#pragma unroll
        for (int i = 16; i < 32; i++) s1 = __fadd_rn(s1, __fmul_rn(rv[i], rv[i]));
        sp[((half << 1) + 0) * 128 + tok] = s0;
        sp[((half << 1) + 1) * 128 + tok] = s1;
#pragma unroll
        for (int i = 0; i < 32; i++)
            xs[(((half << 5) + i) << 7) + tok] = rv[i];
        __syncthreads();
        if (t < 128)
            sx2[t] = __fadd_rn(__fadd_rn(__fadd_rn(sp[0 * 128 + t], sp[1 * 128 + t]),
                                         sp[2 * 128 + t]), sp[3 * 128 + t]);
    }

    // ---- phase 2: load es chunk0 (overwrites xsraw region) ----
#pragma unroll
    for (int q = 0; q < 8; q++) {
        int lin = (q << 8) + t;
        int row = lin >> 5, col = lin & 31;
        cpa16(es_u[0] + (((row << 7) + (col << 2)) << 2),
              g_et + row * KC + (col << 2));
    }
    cpa_commit();

    float bestd[8]; int bestj[8];
#pragma unroll
    for (int i = 0; i < 8; i++) { bestd[i] = __int_as_float(0x7f800000); bestj[i] = 0; }

    cpa_wait0();
    __syncthreads();

    // ---- main loop (A frags via ulonglong2: register pair IS the f32x2) ----
    for (int ch = 0; ch < 8; ch++) {
        int c0 = ch << 7;
        const float* es = (ch & 1) ? esb1 : esb0;
        if (ch < 7) {
            uint32 edst = es_u[(ch + 1) & 1];
            const float* esrc = g_et + ((ch + 1) << 7);
#pragma unroll
            for (int q = 0; q < 8; q++) {
                int lin = (q << 8) + t;
                int row = lin >> 5, col = lin & 31;
                cpa16(edst + (((row << 7) + (col << 2)) << 2),
                      esrc + row * KC + (col << 2));
            }
            cpa_commit();
        }

        ull acc[4][8];
#pragma unroll
        for (int a = 0; a < 4; a++)
#pragma unroll
            for (int b = 0; b < 8; b++) acc[a][b] = 0ull;

        const ulonglong2* XU = (const ulonglong2*)xs;
        const float4* ES = (const float4*)es;
#pragma unroll 8
        for (int kk = 0; kk < 64; kk++) {            // sequential k accumulation
            ulonglong2 A0 = XU[(kk << 5) + rr];      // (tok4rr,4rr+1),(4rr+2,+3)
            ulonglong2 A1 = XU[(kk << 5) + rr + 16];
            float4 b0 = ES[(kk << 5) + cr];
            float4 b1 = ES[(kk << 5) + cr + 16];
            ull xp0 = A0.x, xp1 = A0.y, xp2 = A1.x, xp3 = A1.y;
            float ev[8] = {b0.x, b0.y, b0.z, b0.w, b1.x, b1.y, b1.z, b1.w};
#pragma unroll
            for (int cc = 0; cc < 8; cc++) {
                ull ee = pk2(ev[cc], ev[cc]);
                acc[0][cc] = fma2(xp0, ee, acc[0][cc]);
                acc[1][cc] = fma2(xp1, ee, acc[1][cc]);
                acc[2][cc] = fma2(xp2, ee, acc[2][cc]);
                acc[3][cc] = fma2(xp3, ee, acc[3][cc]);
            }
        }
#pragma unroll
        for (int cc = 0; cc < 8; cc++) {
            int code = c0 + (cr << 2) + cc + ((cc >= 4) ? 60 : 0);
            float e2v = se2[code];
#pragma unroll
            for (int tp = 0; tp < 4; tp++) {
                int tokb = (tp < 2) ? ((rr << 2) + (tp << 1))
                                    : (64 + (rr << 2) + ((tp - 2) << 1));
                float d0, d1; upk2(acc[tp][cc], d0, d1);
                int p0 = tp << 1, p1 = p0 + 1;
                float dist0 = __fadd_rn(__fadd_rn(sx2[tokb], e2v), -2.0f * d0);
                if (dist0 < bestd[p0]) { bestd[p0] = dist0; bestj[p0] = code; }
                float dist1 = __fadd_rn(__fadd_rn(sx2[tokb + 1], e2v), -2.0f * d1);
                if (dist1 < bestd[p1]) { bestd[p1] = dist1; bestj[p1] = code; }
            }
        }
        if (ch < 7) cpa_wait0();
        __syncthreads();
    }

#pragma unroll
    for (int p = 0; p < 8; p++) {
        int tok = (p < 4) ? ((rr << 2) + p) : (60 + (rr << 2) + p);
        redd[cr * 128 + tok] = bestd[p];
        redj[cr * 128 + tok] = bestj[p];
    }
    __syncthreads();
    if (t < 128) {   // lexicographic (dist, j) min == global first-index argmin
        float bd = __int_as_float(0x7f800000); int bj = KC;
        for (int c = 0; c < 16; c++) {
            float d = redd[c * 128 + t]; int j = redj[c * 128 + t];
            if (d < bd || (d == bd && j < bj)) { bd = d; bj = j; }
        }
        g_idx[m0 + t] = bj;
        out_idx_f[m0 + t] = (float)bj;
        sidx[t] = bj;
        atomicAdd(&g_counts[bj], 1);
    }
    __syncthreads();
    // fused dw segment-sum: xs k-major [d][tok], conflict-free reads
#pragma unroll
    for (int p = 0; p < 32; p++) {
        int lin = (p << 8) + t;
        int tok = lin & 127, d = lin >> 7;
        atomicAdd(&g_dwf[(sidx[tok] << 6) + d], xs[(d << 7) + tok]);
    }
}

// ---------------- kernel: quant_out (STE) + mse; batched loads (MLP 8) ------
__global__ void k_quant(const float* __restrict__ X, float* __restrict__ out) {
    __shared__ float ecol[1024];          // row c of g_et == column c of E
    __shared__ double sw[8];
    int pane = blockIdx.x;                // b*64 + c
    int c = pane & 63, b = pane >> 6;
    int t = threadIdx.x;
    const float4* ec4 = (const float4*)(g_et + (size_t)c * KC);
    float4 ecv = ec4[t];

    size_t base = (size_t)pane << 12;
    const float4* X4 = (const float4*)(X + base);
    float4* O4 = (float4*)(out + base);
    const int4* I4 = (const int4*)(g_idx + ((size_t)b << 12));

    float4 x[4]; int4 kv[4];
#pragma unroll
    for (int r = 0; r < 4; r++) { x[r] = X4[(r << 8) + t]; kv[r] = I4[(r << 8) + t]; }

    ((float4*)ecol)[t] = ecv;
    __syncthreads();

    float accf = 0.f;
#pragma unroll
    for (int r = 0; r < 4; r++) {
        float q0 = ecol[kv[r].x], q1 = ecol[kv[r].y];
        float q2 = ecol[kv[r].z], q3 = ecol[kv[r].w];
        float d0 = __fsub_rn(q0, x[r].x), d1 = __fsub_rn(q1, x[r].y);
        float d2 = __fsub_rn(q2, x[r].z), d3 = __fsub_rn(q3, x[r].w);
        float4 o;
        o.x = __fadd_rn(x[r].x, d0); o.y = __fadd_rn(x[r].y, d1);
        o.z = __fadd_rn(x[r].z, d2); o.w = __fadd_rn(x[r].w, d3);
        O4[(r << 8) + t] = o;
        accf += d0 * d0 + d1 * d1 + d2 * d2 + d3 * d3;
    }
    double acc = (double)accf;
#pragma unroll
    for (int o = 16; o; o >>= 1) acc += __shfl_down_sync(0xffffffffu, acc, o);
    if ((t & 31) == 0) sw[t >> 5] = acc;
    __syncthreads();
    if (t == 0) {
        double s = 0.0;
        for (int i = 0; i < 8; i++) s += sw[i];
        atomicAdd(&g_mse, s);
    }
}

// ---------------- kernel: entropy / loss / new_cs ----------------------------
__global__ void k_final(const float* __restrict__ cs_in, float* __restrict__ out) {
    __shared__ double sh[1024];
    int t = threadIdx.x;
    int c = g_counts[t];
    double p = (double)c / 65536.0;
    sh[t] = -p * log(p + 1e-10);
    __syncthreads();
    for (int s = 512; s > 0; s >>= 1) { if (t < s) sh[t] += sh[t + s]; __syncthreads(); }
    double entropy = sh[0];
    __syncthreads();
    double pre = (double)cs_in[t] * 0.99 + 0.01 * (double)c;
    sh[t] = pre;
    __syncthreads();
    for (int s = 512; s > 0; s >>= 1) { if (t < s) sh[t] += sh[t + s]; __syncthreads(); }
    double n_tot = sh[0];
    double ncs = (pre + 1e-5) / (n_tot + 1024.0 * 1e-5) * n_tot;
    out[OFF_CS + t] = (float)ncs;
    g_newcs[t] = (float)ncs;
    if (t == 0) {
        double mse = g_mse / (double)NELEM;
        out[OFF_LOSS] = (float)(mse * 1.25 + entropy);
    }
}

// ---------------- kernel: new_ema_w + new_embedding --------------------------
__global__ void k_ema(const float* __restrict__ ema_w, float* __restrict__ out) {
    int i = blockIdx.x * 256 + threadIdx.x;
    float w = ema_w[i] * 0.99f + 0.01f * g_dwf[i];
    out[OFF_EMAW + i] = w;
    out[OFF_EMB + i] = w / g_newcs[i >> 6];
}

// ---------------- launcher ---------------------------------------------------
extern "C" void kernel_launch(void* const* d_in, const int* in_sizes, int n_in,
                              void* d_out, int out_size) {
    const float* X   = (const float*)d_in[0];
    const float* E   = (const float*)d_in[1];
    const float* R   = (const float*)d_in[2];
    const float* CS  = (const float*)d_in[3];
    const float* EW  = (const float*)d_in[4];
    float* out = (float*)d_out;

    static bool attr_set = false;
    if (!attr_set) {
        cudaFuncSetAttribute(k_gemm, cudaFuncAttributeMaxDynamicSharedMemorySize, GEMM_SMEM);
        attr_set = true;
    }

    k_init<<<260, 256>>>(E);
    k_gemm<<<512, 256, GEMM_SMEM>>>(E, X, R, out + OFF_IDX);
    k_quant<<<1024, 256>>>(X, out);
    k_final<<<1, 1024>>>(CS, out);
    k_ema<<<256, 256>>>(EW, out);
}

// round 16
// speedup vs baseline: 1.0492x; 1.0492x over previous
#include <cuda_runtime.h>
#include <math.h>

#define N_TOK 65536
#define DD 64
#define KC 1024
#define NELEM 4194304
#define OFF_LOSS 4194304
#define OFF_IDX  4194305
#define OFF_EMB  4259841
#define OFF_CS   4325377
#define OFF_EMAW 4326401

// ---------------- scratch (device globals; no allocations allowed) ----------
__device__ float  g_et[DD * KC];          // E transposed [d][k] (k-major rows)
__device__ float  g_e2[KC];
__device__ int    g_idx[N_TOK];
__device__ int    g_counts[KC];
__device__ float  g_dwf[KC * DD];
__device__ double g_mse;
__device__ float  g_newcs[KC];

typedef unsigned long long ull;
typedef unsigned int uint32;

__device__ __forceinline__ ull pk2(float lo, float hi) {
    ull r; asm("mov.b64 %0, {%1, %2};" : "=l"(r) : "f"(lo), "f"(hi)); return r;
}
__device__ __forceinline__ void upk2(ull v, float &lo, float &hi) {
    asm("mov.b64 {%0, %1}, %2;" : "=f"(lo), "=f"(hi) : "l"(v));
}
__device__ __forceinline__ ull fma2(ull a, ull b, ull c) {
    ull d; asm("fma.rn.f32x2 %0, %1, %2, %3;" : "=l"(d) : "l"(a), "l"(b), "l"(c)); return d;
}
__device__ __forceinline__ void cpa16(uint32 dst, const void* src) {
    asm volatile("cp.async.cg.shared.global [%0], [%1], 16;" :: "r"(dst), "l"(src));
}
__device__ __forceinline__ void cpa_commit() { asm volatile("cp.async.commit_group;"); }
__device__ __forceinline__ void cpa_wait0()  { asm volatile("cp.async.wait_group 0;"); }

// ---------------- kernel: zero scratch + e2 + E transpose (merged) ----------
__global__ void k_init(const float* __restrict__ E) {
    int b = blockIdx.x, t = threadIdx.x;
    if (b < 256) {
        int i = b * 256 + t;                 // 65536: covers all of g_dwf
        g_dwf[i] = 0.f;
        if (i < KC) g_counts[i] = 0;
        if (i == 0) g_mse = 0.0;
    } else {
        int k = (b - 256) * 256 + t;         // 0..1023
        const float4* e = (const float4*)(E + ((size_t)k << 6));
        float s = 0.f;
#pragma unroll
        for (int q = 0; q < 16; q++) {
            float4 v = e[q];
            int d = q << 2;
            g_et[(d + 0) * KC + k] = v.x;    // coalesced over k
            g_et[(d + 1) * KC + k] = v.y;
            g_et[(d + 2) * KC + k] = v.z;
            g_et[(d + 3) * KC + k] = v.w;
            s = __fadd_rn(s, __fmul_rn(v.x, v.x));
            s = __fadd_rn(s, __fmul_rn(v.y, v.y));
            s = __fadd_rn(s, __fmul_rn(v.z, v.z));
            s = __fadd_rn(s, __fmul_rn(v.w, v.w));
        }
        g_e2[k] = s;
    }
}

// ---------------- kernel: fused rotation + distance GEMM + argmin + stats ---
#define GEMM_SMEM (32768 * 3 + 4096 + 512 + 512)
__global__ void __launch_bounds__(256, 2) k_gemm(const float* __restrict__ E,
                                                 const float* __restrict__ X,
                                                 const float* __restrict__ Rg,
                                                 float* __restrict__ out_idx_f) {
    extern __shared__ char sm[];
    float* xs   = (float*)sm;                        // [64][128] k-major x_rot
    float* esb0 = (float*)(sm + 32768);              // [64][128]
    float* esb1 = (float*)(sm + 65536);
    float* se2  = (float*)(sm + 98304);              // [1024]
    float* sx2  = (float*)(sm + 102400);             // [128]
    int*   sidx = (int*)(sm + 102912);               // [128]
    // prologue overlays (dead before es buffers are loaded):
    float* xsraw = esb0;                             // [64 c][128 tok] raw X
    float* Rs    = esb1;                             // [64][64]
    float* sp    = (float*)(sm + 65536 + 16384);     // [4][128] x2 partials
    float* redd = esb0;                              // overlay after loop
    int*   redj = (int*)(sm + 32768 + 8192);

    int t = threadIdx.x;
    int lane = t & 31, w = t >> 5;
    int rr = ((w >> 1) << 2) | (lane >> 3);
    int cr = ((w & 1) << 3) | (lane & 7);
    int m0 = blockIdx.x << 7;

    uint32 es_u[2] = { (uint32)__cvta_generic_to_shared(esb0),
                       (uint32)__cvta_generic_to_shared(esb1) };
    uint32 se2_u  = (uint32)__cvta_generic_to_shared(se2);

    // ---- phase 0: async-load X block rows (32KB), R (16KB), e2 (4KB) ----
    {
        const float* Xblk = X + ((size_t)(m0 >> 12) << 18) + (m0 & 4095);
#pragma unroll
        for (int q = 0; q < 8; q++) {                // xsraw: 2048 x 16B = 32KB
            int lin = (q << 8) + t;
            int row = lin >> 5, seg = lin & 31;
            cpa16(es_u[0] + (((row << 7) + (seg << 2)) << 2),
                  Xblk + (size_t)row * 4096 + (seg << 2));
        }
#pragma unroll
        for (int q = 0; q < 4; q++) {                // Rs: 1024 x 16B = 16KB
            int lin = (q << 8) + t;
            cpa16(es_u[1] + (lin << 4), Rg + (lin << 2));
        }
        cpa16(se2_u + (t << 4), g_e2 + (t << 2));    // se2: 256 x 16B = 4KB
        cpa_commit();
        cpa_wait0();
        __syncthreads();
    }

    // ---- phase 1: rotate 128 tokens (bit-exact vs old k_rotate) ----
    {
        int tok = t & 127, half = t >> 7;            // half: dims [32h, 32h+32)
        ull r2[16];
#pragma unroll
        for (int i = 0; i < 16; i++) r2[i] = 0ull;
        const ull* R2base = (const ull*)(Rs + (half << 5));
#pragma unroll 8
        for (int c = 0; c < 64; c++) {               // ascending c, fma chains
            float xv = xsraw[(c << 7) + tok];
            ull xd = pk2(xv, xv);
            const ull* Rrow = R2base + (c << 5);
#pragma unroll
            for (int i = 0; i < 16; i++)
                r2[i] = fma2(xd, Rrow[i], r2[i]);
        }
        float rv[32];
#pragma unroll
        for (int i = 0; i < 16; i++) upk2(r2[i], rv[2 * i], rv[2 * i + 1]);
        float s0 = 0.f, s1 = 0.f;
#pragma unroll
        for (int i = 0; i < 16; i++) s0 = __fadd_rn(s0, __fmul_rn(rv[i], rv[i]));
#pragma unroll
        for (int i = 16; i < 32; i++) s1 = __fadd_rn(s1, __fmul_rn(rv[i], rv[i]));
        sp[((half << 1) + 0) * 128 + tok] = s0;
        sp[((half << 1) + 1) * 128 + tok] = s1;
#pragma unroll
        for (int i = 0; i < 32; i++)
            xs[(((half << 5) + i) << 7) + tok] = rv[i];
        __syncthreads();
        if (t < 128)
            sx2[t] = __fadd_rn(__fadd_rn(__fadd_rn(sp[0 * 128 + t], sp[1 * 128 + t]),
                                         sp[2 * 128 + t]), sp[3 * 128 + t]);
    }

    // ---- phase 2: load es chunk0 (overwrites xsraw region) ----
#pragma unroll
    for (int q = 0; q < 8; q++) {
        int lin = (q << 8) + t;
        int row = lin >> 5, col = lin & 31;
        cpa16(es_u[0] + (((row << 7) + (col << 2)) << 2),
              g_et + row * KC + (col << 2));
    }
    cpa_commit();

    float bestd[8]; int bestj[8];
#pragma unroll
    for (int i = 0; i < 8; i++) { bestd[i] = __int_as_float(0x7f800000); bestj[i] = 0; }

    cpa_wait0();
    __syncthreads();

    // ---- main loop ----
    for (int ch = 0; ch < 8; ch++) {
        int c0 = ch << 7;
        const float* es = (ch & 1) ? esb1 : esb0;
        if (ch < 7) {
            uint32 edst = es_u[(ch + 1) & 1];
            const float* esrc = g_et + ((ch + 1) << 7);
#pragma unroll
            for (int q = 0; q < 8; q++) {
                int lin = (q << 8) + t;
                int row = lin >> 5, col = lin & 31;
                cpa16(edst + (((row << 7) + (col << 2)) << 2),
                      esrc + row * KC + (col << 2));
            }
            cpa_commit();
        }

        ull acc[4][8];
#pragma unroll
        for (int a = 0; a < 4; a++)
#pragma unroll
            for (int b = 0; b < 8; b++) acc[a][b] = 0ull;

        const ulonglong2* XU = (const ulonglong2*)xs;
        const float4* ES = (const float4*)es;
#pragma unroll 8
        for (int kk = 0; kk < 64; kk++) {            // sequential k accumulation
            ulonglong2 A0 = XU[(kk << 5) + rr];
            ulonglong2 A1 = XU[(kk << 5) + rr + 16];
            float4 b0 = ES[(kk << 5) + cr];
            float4 b1 = ES[(kk << 5) + cr + 16];
            ull xp0 = A0.x, xp1 = A0.y, xp2 = A1.x, xp3 = A1.y;
            float ev[8] = {b0.x, b0.y, b0.z, b0.w, b1.x, b1.y, b1.z, b1.w};
#pragma unroll
            for (int cc = 0; cc < 8; cc++) {
                ull ee = pk2(ev[cc], ev[cc]);
                acc[0][cc] = fma2(xp0, ee, acc[0][cc]);
                acc[1][cc] = fma2(xp1, ee, acc[1][cc]);
                acc[2][cc] = fma2(xp2, ee, acc[2][cc]);
                acc[3][cc] = fma2(xp3, ee, acc[3][cc]);
            }
        }
#pragma unroll
        for (int cc = 0; cc < 8; cc++) {
            int code = c0 + (cr << 2) + cc + ((cc >= 4) ? 60 : 0);
            float e2v = se2[code];
#pragma unroll
            for (int tp = 0; tp < 4; tp++) {
                int tokb = (tp < 2) ? ((rr << 2) + (tp << 1))
                                    : (64 + (rr << 2) + ((tp - 2) << 1));
                float d0, d1; upk2(acc[tp][cc], d0, d1);
                int p0 = tp << 1, p1 = p0 + 1;
                float dist0 = __fadd_rn(__fadd_rn(sx2[tokb], e2v), -2.0f * d0);
                if (dist0 < bestd[p0]) { bestd[p0] = dist0; bestj[p0] = code; }
                float dist1 = __fadd_rn(__fadd_rn(sx2[tokb + 1], e2v), -2.0f * d1);
                if (dist1 < bestd[p1]) { bestd[p1] = dist1; bestj[p1] = code; }
            }
        }
        if (ch < 7) cpa_wait0();
        __syncthreads();
    }

#pragma unroll
    for (int p = 0; p < 8; p++) {
        int tok = (p < 4) ? ((rr << 2) + p) : (60 + (rr << 2) + p);
        redd[cr * 128 + tok] = bestd[p];
        redj[cr * 128 + tok] = bestj[p];
    }
    __syncthreads();
    if (t < 128) {   // lexicographic (dist, j) min == global first-index argmin
        float bd = __int_as_float(0x7f800000); int bj = KC;
        for (int c = 0; c < 16; c++) {
            float d = redd[c * 128 + t]; int j = redj[c * 128 + t];
            if (d < bd || (d == bd && j < bj)) { bd = d; bj = j; }
        }
        g_idx[m0 + t] = bj;
        out_idx_f[m0 + t] = (float)bj;
        sidx[t] = bj;
        atomicAdd(&g_counts[bj], 1);
    }
    __syncthreads();
    // fused dw segment-sum: xs k-major [d][tok], conflict-free reads
#pragma unroll
    for (int p = 0; p < 32; p++) {
        int lin = (p << 8) + t;
        int tok = lin & 127, d = lin >> 7;
        atomicAdd(&g_dwf[(sidx[tok] << 6) + d], xs[(d << 7) + tok]);
    }
}

// ---------------- kernel: quant_out (STE) + mse; batched loads (MLP 8) ------
__global__ void k_quant(const float* __restrict__ X, float* __restrict__ out) {
    __shared__ float ecol[1024];          // row c of g_et == column c of E
    __shared__ double sw[8];
    int pane = blockIdx.x;                // b*64 + c
    int c = pane & 63, b = pane >> 6;
    int t = threadIdx.x;
    const float4* ec4 = (const float4*)(g_et + (size_t)c * KC);
    float4 ecv = ec4[t];

    size_t base = (size_t)pane << 12;
    const float4* X4 = (const float4*)(X + base);
    float4* O4 = (float4*)(out + base);
    const int4* I4 = (const int4*)(g_idx + ((size_t)b << 12));

    float4 x[4]; int4 kv[4];
#pragma unroll
    for (int r = 0; r < 4; r++) { x[r] = X4[(r << 8) + t]; kv[r] = I4[(r << 8) + t]; }

    ((float4*)ecol)[t] = ecv;
    __syncthreads();

    float accf = 0.f;
#pragma unroll
    for (int r = 0; r < 4; r++) {
        float q0 = ecol[kv[r].x], q1 = ecol[kv[r].y];
        float q2 = ecol[kv[r].z], q3 = ecol[kv[r].w];
        float d0 = __fsub_rn(q0, x[r].x), d1 = __fsub_rn(q1, x[r].y);
        float d2 = __fsub_rn(q2, x[r].z), d3 = __fsub_rn(q3, x[r].w);
        float4 o;
        o.x = __fadd_rn(x[r].x, d0); o.y = __fadd_rn(x[r].y, d1);
        o.z = __fadd_rn(x[r].z, d2); o.w = __fadd_rn(x[r].w, d3);
        O4[(r << 8) + t] = o;
        accf += d0 * d0 + d1 * d1 + d2 * d2 + d3 * d3;
    }
    double acc = (double)accf;
#pragma unroll
    for (int o = 16; o; o >>= 1) acc += __shfl_down_sync(0xffffffffu, acc, o);
    if ((t & 31) == 0) sw[t >> 5] = acc;
    __syncthreads();
    if (t == 0) {
        double s = 0.0;
        for (int i = 0; i < 8; i++) s += sw[i];
        atomicAdd(&g_mse, s);
    }
}

// ---------------- kernel: entropy / loss / new_cs (fp32 log, shuffle reduce) -
__global__ void k_final(const float* __restrict__ cs_in, float* __restrict__ out) {
    __shared__ double s_ent[32], s_tot[32];
    int t = threadIdx.x;                  // 1024 threads
    int c = g_counts[t];
    float p = (float)c / 65536.0f;
    double ent = -(double)p * (double)logf(p + 1e-10f);   // fast MUFU-based log
    double pre = (double)cs_in[t] * 0.99 + 0.01 * (double)c;
    double tot = pre;
#pragma unroll
    for (int o = 16; o; o >>= 1) {
        ent += __shfl_down_sync(0xffffffffu, ent, o);
        tot += __shfl_down_sync(0xffffffffu, tot, o);
    }
    if ((t & 31) == 0) { s_ent[t >> 5] = ent; s_tot[t >> 5] = tot; }
    __syncthreads();
    if (t < 32) {
        double e = s_ent[t], n = s_tot[t];
#pragma unroll
        for (int o = 16; o; o >>= 1) {
            e += __shfl_down_sync(0xffffffffu, e, o);
            n += __shfl_down_sync(0xffffffffu, n, o);
        }
        if (t == 0) { s_ent[0] = e; s_tot[0] = n; }
    }
    __syncthreads();
    double entropy = s_ent[0], n_tot = s_tot[0];
    double ncs = (pre + 1e-5) / (n_tot + 1024.0 * 1e-5) * n_tot;
    out[OFF_CS + t] = (float)ncs;
    g_newcs[t] = (float)ncs;
    if (t == 0) {
        double mse = g_mse / (double)NELEM;
        out[OFF_LOSS] = (float)(mse * 1.25 + entropy);
    }
}

// ---------------- kernel: new_ema_w + new_embedding --------------------------
__global__ void k_ema(const float* __restrict__ ema_w, float* __restrict__ out) {
    int i = blockIdx.x * 256 + threadIdx.x;
    float w = ema_w[i] * 0.99f + 0.01f * g_dwf[i];
    out[OFF_EMAW + i] = w;
    out[OFF_EMB + i] = w / g_newcs[i >> 6];
}

// ---------------- launcher ---------------------------------------------------
extern "C" void kernel_launch(void* const* d_in, const int* in_sizes, int n_in,
                              void* d_out, int out_size) {
    const float* X   = (const float*)d_in[0];
    const float* E   = (const float*)d_in[1];
    const float* R   = (const float*)d_in[2];
    const float* CS  = (const float*)d_in[3];
    const float* EW  = (const float*)d_in[4];
    float* out = (float*)d_out;

    static bool attr_set = false;
    if (!attr_set) {
        cudaFuncSetAttribute(k_gemm, cudaFuncAttributeMaxDynamicSharedMemorySize, GEMM_SMEM);
        attr_set = true;
    }

    k_init<<<260, 256>>>(E);
    k_gemm<<<512, 256, GEMM_SMEM>>>(E, X, R, out + OFF_IDX);
    k_quant<<<1024, 256>>>(X, out);
    k_final<<<1, 1024>>>(CS, out);
    k_ema<<<256, 256>>>(EW, out);
}

// round 17
// speedup vs baseline: 1.0668x; 1.0168x over previous
#include <cuda_runtime.h>
#include <math.h>

#define N_TOK 65536
#define DD 64
#define KC 1024
#define NELEM 4194304
#define OFF_LOSS 4194304
#define OFF_IDX  4194305
#define OFF_EMB  4259841
#define OFF_CS   4325377
#define OFF_EMAW 4326401

// ---------------- scratch (device globals; no allocations allowed) ----------
__device__ float  g_et[DD * KC];          // E transposed [d][k] (k-major rows)
__device__ float  g_e2[KC];
__device__ int    g_idx[N_TOK];
__device__ int    g_counts[KC];
__device__ float  g_dwf[KC * DD];
__device__ double g_mse;
__device__ double g_entropy;
__device__ float  g_newcs[KC];

typedef unsigned long long ull;
typedef unsigned int uint32;

__device__ __forceinline__ ull pk2(float lo, float hi) {
    ull r; asm("mov.b64 %0, {%1, %2};" : "=l"(r) : "f"(lo), "f"(hi)); return r;
}
__device__ __forceinline__ void upk2(ull v, float &lo, float &hi) {
    asm("mov.b64 {%0, %1}, %2;" : "=f"(lo), "=f"(hi) : "l"(v));
}
__device__ __forceinline__ ull fma2(ull a, ull b, ull c) {
    ull d; asm("fma.rn.f32x2 %0, %1, %2, %3;" : "=l"(d) : "l"(a), "l"(b), "l"(c)); return d;
}
__device__ __forceinline__ void cpa16(uint32 dst, const void* src) {
    asm volatile("cp.async.cg.shared.global [%0], [%1], 16;" :: "r"(dst), "l"(src));
}
__device__ __forceinline__ void cpa_commit() { asm volatile("cp.async.commit_group;"); }
__device__ __forceinline__ void cpa_wait0()  { asm volatile("cp.async.wait_group 0;"); }

// ---------------- kernel: zero scratch + e2 + E transpose (merged) ----------
__global__ void k_init(const float* __restrict__ E) {
    int b = blockIdx.x, t = threadIdx.x;
    if (b < 256) {
        int i = b * 256 + t;                 // 65536: covers all of g_dwf
        g_dwf[i] = 0.f;
        if (i < KC) g_counts[i] = 0;
        if (i == 0) g_mse = 0.0;
    } else {
        int k = (b - 256) * 256 + t;         // 0..1023
        const float4* e = (const float4*)(E + ((size_t)k << 6));
        float s = 0.f;
#pragma unroll
        for (int q = 0; q < 16; q++) {
            float4 v = e[q];
            int d = q << 2;
            g_et[(d + 0) * KC + k] = v.x;    // coalesced over k
            g_et[(d + 1) * KC + k] = v.y;
            g_et[(d + 2) * KC + k] = v.z;
            g_et[(d + 3) * KC + k] = v.w;
            s = __fadd_rn(s, __fmul_rn(v.x, v.x));
            s = __fadd_rn(s, __fmul_rn(v.y, v.y));
            s = __fadd_rn(s, __fmul_rn(v.z, v.z));
            s = __fadd_rn(s, __fmul_rn(v.w, v.w));
        }
        g_e2[k] = s;
    }
}

// ---------------- kernel: fused rotation + distance GEMM + argmin + stats ---
#define GEMM_SMEM (32768 * 3 + 4096 + 512 + 512)
__global__ void __launch_bounds__(256, 2) k_gemm(const float* __restrict__ E,
                                                 const float* __restrict__ X,
                                                 const float* __restrict__ Rg,
                                                 float* __restrict__ out_idx_f) {
    extern __shared__ char sm[];
    float* xs   = (float*)sm;                        // [64][128] k-major x_rot
    float* esb0 = (float*)(sm + 32768);              // [64][128]
    float* esb1 = (float*)(sm + 65536);
    float* se2  = (float*)(sm + 98304);              // [1024]
    float* sx2  = (float*)(sm + 102400);             // [128]
    int*   sidx = (int*)(sm + 102912);               // [128]
    // prologue overlays (dead before es buffers are loaded):
    float* xsraw = esb0;                             // [64 c][128 tok] raw X
    float* Rs    = esb1;                             // [64][64]
    float* sp    = (float*)(sm + 65536 + 16384);     // [4][128] x2 partials
    float* redd = esb0;                              // overlay after loop
    int*   redj = (int*)(sm + 32768 + 8192);

    int t = threadIdx.x;
    int lane = t & 31, w = t >> 5;
    int rr = ((w >> 1) << 2) | (lane >> 3);
    int cr = ((w & 1) << 3) | (lane & 7);
    int m0 = blockIdx.x << 7;

    uint32 es_u[2] = { (uint32)__cvta_generic_to_shared(esb0),
                       (uint32)__cvta_generic_to_shared(esb1) };
    uint32 se2_u  = (uint32)__cvta_generic_to_shared(se2);

    // ---- phase 0: async-load X block rows (32KB), R (16KB), e2 (4KB) ----
    {
        const float* Xblk = X + ((size_t)(m0 >> 12) << 18) + (m0 & 4095);
#pragma unroll
        for (int q = 0; q < 8; q++) {                // xsraw: 2048 x 16B = 32KB
            int lin = (q << 8) + t;
            int row = lin >> 5, seg = lin & 31;
            cpa16(es_u[0] + (((row << 7) + (seg << 2)) << 2),
                  Xblk + (size_t)row * 4096 + (seg << 2));
        }
#pragma unroll
        for (int q = 0; q < 4; q++) {                // Rs: 1024 x 16B = 16KB
            int lin = (q << 8) + t;
            cpa16(es_u[1] + (lin << 4), Rg + (lin << 2));
        }
        cpa16(se2_u + (t << 4), g_e2 + (t << 2));    // se2: 256 x 16B = 4KB
        cpa_commit();
        cpa_wait0();
        __syncthreads();
    }

    // ---- phase 1: rotate 128 tokens (bit-exact vs old k_rotate) ----
    {
        int tok = t & 127, half = t >> 7;            // half: dims [32h, 32h+32)
        ull r2[16];
#pragma unroll
        for (int i = 0; i < 16; i++) r2[i] = 0ull;
        const ull* R2base = (const ull*)(Rs + (half << 5));
#pragma unroll 8
        for (int c = 0; c < 64; c++) {               // ascending c, fma chains
            float xv = xsraw[(c << 7) + tok];
            ull xd = pk2(xv, xv);
            const ull* Rrow = R2base + (c << 5);
#pragma unroll
            for (int i = 0; i < 16; i++)
                r2[i] = fma2(xd, Rrow[i], r2[i]);
        }
        float rv[32];
#pragma unroll
        for (int i = 0; i < 16; i++) upk2(r2[i], rv[2 * i], rv[2 * i + 1]);
        float s0 = 0.f, s1 = 0.f;
#pragma unroll
        for (int i = 0; i < 16; i++) s0 = __fadd_rn(s0, __fmul_rn(rv[i], rv[i]));
#pragma unroll
        for (int i = 16; i < 32; i++) s1 = __fadd_rn(s1, __fmul_rn(rv[i], rv[i]));
        sp[((half << 1) + 0) * 128 + tok] = s0;
        sp[((half << 1) + 1) * 128 + tok] = s1;
#pragma unroll
        for (int i = 0; i < 32; i++)
            xs[(((half << 5) + i) << 7) + tok] = rv[i];
        __syncthreads();
        if (t < 128)
            sx2[t] = __fadd_rn(__fadd_rn(__fadd_rn(sp[0 * 128 + t], sp[1 * 128 + t]),
                                         sp[2 * 128 + t]), sp[3 * 128 + t]);
    }

    // ---- phase 2: load es chunk0 (overwrites xsraw region) ----
#pragma unroll
    for (int q = 0; q < 8; q++) {
        int lin = (q << 8) + t;
        int row = lin >> 5, col = lin & 31;
        cpa16(es_u[0] + (((row << 7) + (col << 2)) << 2),
              g_et + row * KC + (col << 2));
    }
    cpa_commit();

    float bestd[8]; int bestj[8];
#pragma unroll
    for (int i = 0; i < 8; i++) { bestd[i] = __int_as_float(0x7f800000); bestj[i] = 0; }

    cpa_wait0();
    __syncthreads();

    // ---- main loop ----
    for (int ch = 0; ch < 8; ch++) {
        int c0 = ch << 7;
        const float* es = (ch & 1) ? esb1 : esb0;
        if (ch < 7) {
            uint32 edst = es_u[(ch + 1) & 1];
            const float* esrc = g_et + ((ch + 1) << 7);
#pragma unroll
            for (int q = 0; q < 8; q++) {
                int lin = (q << 8) + t;
                int row = lin >> 5, col = lin & 31;
                cpa16(edst + (((row << 7) + (col << 2)) << 2),
                      esrc + row * KC + (col << 2));
            }
            cpa_commit();
        }

        ull acc[4][8];
#pragma unroll
        for (int a = 0; a < 4; a++)
#pragma unroll
            for (int b = 0; b < 8; b++) acc[a][b] = 0ull;

        const ulonglong2* XU = (const ulonglong2*)xs;
        const float4* ES = (const float4*)es;
#pragma unroll 8
        for (int kk = 0; kk < 64; kk++) {            // sequential k accumulation
            ulonglong2 A0 = XU[(kk << 5) + rr];
            ulonglong2 A1 = XU[(kk << 5) + rr + 16];
            float4 b0 = ES[(kk << 5) + cr];
            float4 b1 = ES[(kk << 5) + cr + 16];
            ull xp0 = A0.x, xp1 = A0.y, xp2 = A1.x, xp3 = A1.y;
            float ev[8] = {b0.x, b0.y, b0.z, b0.w, b1.x, b1.y, b1.z, b1.w};
#pragma unroll
            for (int cc = 0; cc < 8; cc++) {
                ull ee = pk2(ev[cc], ev[cc]);
                acc[0][cc] = fma2(xp0, ee, acc[0][cc]);
                acc[1][cc] = fma2(xp1, ee, acc[1][cc]);
                acc[2][cc] = fma2(xp2, ee, acc[2][cc]);
                acc[3][cc] = fma2(xp3, ee, acc[3][cc]);
            }
        }
#pragma unroll
        for (int cc = 0; cc < 8; cc++) {
            int code = c0 + (cr << 2) + cc + ((cc >= 4) ? 60 : 0);
            float e2v = se2[code];
#pragma unroll
            for (int tp = 0; tp < 4; tp++) {
                int tokb = (tp < 2) ? ((rr << 2) + (tp << 1))
                                    : (64 + (rr << 2) + ((tp - 2) << 1));
                float d0, d1; upk2(acc[tp][cc], d0, d1);
                int p0 = tp << 1, p1 = p0 + 1;
                float dist0 = __fadd_rn(__fadd_rn(sx2[tokb], e2v), -2.0f * d0);
                if (dist0 < bestd[p0]) { bestd[p0] = dist0; bestj[p0] = code; }
                float dist1 = __fadd_rn(__fadd_rn(sx2[tokb + 1], e2v), -2.0f * d1);
                if (dist1 < bestd[p1]) { bestd[p1] = dist1; bestj[p1] = code; }
            }
        }
        if (ch < 7) cpa_wait0();
        __syncthreads();
    }

#pragma unroll
    for (int p = 0; p < 8; p++) {
        int tok = (p < 4) ? ((rr << 2) + p) : (60 + (rr << 2) + p);
        redd[cr * 128 + tok] = bestd[p];
        redj[cr * 128 + tok] = bestj[p];
    }
    __syncthreads();
    if (t < 128) {   // lexicographic (dist, j) min == global first-index argmin
        float bd = __int_as_float(0x7f800000); int bj = KC;
        for (int c = 0; c < 16; c++) {
            float d = redd[c * 128 + t]; int j = redj[c * 128 + t];
            if (d < bd || (d == bd && j < bj)) { bd = d; bj = j; }
        }
        g_idx[m0 + t] = bj;
        out_idx_f[m0 + t] = (float)bj;
        sidx[t] = bj;
        atomicAdd(&g_counts[bj], 1);
    }
    __syncthreads();
    // fused dw segment-sum: xs k-major [d][tok], conflict-free reads
#pragma unroll
    for (int p = 0; p < 32; p++) {
        int lin = (p << 8) + t;
        int tok = lin & 127, d = lin >> 7;
        atomicAdd(&g_dwf[(sidx[tok] << 6) + d], xs[(d << 7) + tok]);
    }
}

// ---------------- kernel: quant_out + mse; block 1024 = cs/entropy reduce ---
__global__ void k_quant(const float* __restrict__ X, const float* __restrict__ cs_in,
                        float* __restrict__ out) {
    int t = threadIdx.x;
    if (blockIdx.x == 1024) {
        // hidden reduction block: entropy, n_tot, new_cs (counts final post-gemm)
        __shared__ double s_ent[8], s_tot[8];
        __shared__ double s_ntot;
        double ent = 0.0, tot = 0.0, pre[4];
#pragma unroll
        for (int r = 0; r < 4; r++) {
            int k = (r << 8) + t;
            int c = g_counts[k];
            float p = (float)c / 65536.0f;
            ent += -(double)p * (double)logf(p + 1e-10f);
            pre[r] = (double)cs_in[k] * 0.99 + 0.01 * (double)c;
            tot += pre[r];
        }
#pragma unroll
        for (int o = 16; o; o >>= 1) {
            ent += __shfl_down_sync(0xffffffffu, ent, o);
            tot += __shfl_down_sync(0xffffffffu, tot, o);
        }
        if ((t & 31) == 0) { s_ent[t >> 5] = ent; s_tot[t >> 5] = tot; }
        __syncthreads();
        if (t == 0) {
            double e = 0.0, n = 0.0;
            for (int i = 0; i < 8; i++) { e += s_ent[i]; n += s_tot[i]; }
            g_entropy = e;
            s_ntot = n;
        }
        __syncthreads();
        double n_tot = s_ntot;
#pragma unroll
        for (int r = 0; r < 4; r++) {
            int k = (r << 8) + t;
            double ncs = (pre[r] + 1e-5) / (n_tot + 1024.0 * 1e-5) * n_tot;
            out[OFF_CS + k] = (float)ncs;
            g_newcs[k] = (float)ncs;
        }
        return;
    }

    __shared__ float ecol[1024];          // row c of g_et == column c of E
    __shared__ double sw[8];
    int pane = blockIdx.x;                // b*64 + c
    int c = pane & 63, b = pane >> 6;
    const float4* ec4 = (const float4*)(g_et + (size_t)c * KC);
    float4 ecv = ec4[t];

    size_t base = (size_t)pane << 12;
    const float4* X4 = (const float4*)(X + base);
    float4* O4 = (float4*)(out + base);
    const int4* I4 = (const int4*)(g_idx + ((size_t)b << 12));

    float4 x[4]; int4 kv[4];
#pragma unroll
    for (int r = 0; r < 4; r++) { x[r] = X4[(r << 8) + t]; kv[r] = I4[(r << 8) + t]; }

    ((float4*)ecol)[t] = ecv;
    __syncthreads();

    float accf = 0.f;
#pragma unroll
    for (int r = 0; r < 4; r++) {
        float q0 = ecol[kv[r].x], q1 = ecol[kv[r].y];
        float q2 = ecol[kv[r].z], q3 = ecol[kv[r].w];
        float d0 = __fsub_rn(q0, x[r].x), d1 = __fsub_rn(q1, x[r].y);
        float d2 = __fsub_rn(q2, x[r].z), d3 = __fsub_rn(q3, x[r].w);
        float4 o;
        o.x = __fadd_rn(x[r].x, d0); o.y = __fadd_rn(x[r].y, d1);
        o.z = __fadd_rn(x[r].z, d2); o.w = __fadd_rn(x[r].w, d3);
        O4[(r << 8) + t] = o;
        accf += d0 * d0 + d1 * d1 + d2 * d2 + d3 * d3;
    }
    double acc = (double)accf;
#pragma unroll
    for (int o = 16; o; o >>= 1) acc += __shfl_down_sync(0xffffffffu, acc, o);
    if ((t & 31) == 0) sw[t >> 5] = acc;
    __syncthreads();
    if (t == 0) {
        double s = 0.0;
        for (int i = 0; i < 8; i++) s += sw[i];
        atomicAdd(&g_mse, s);
    }
}

// ---------------- kernel: new_ema_w + new_embedding + loss ------------------
__global__ void k_ema(const float* __restrict__ ema_w, float* __restrict__ out) {
    int i = blockIdx.x * 256 + threadIdx.x;
    float w = ema_w[i] * 0.99f + 0.01f * g_dwf[i];
    out[OFF_EMAW + i] = w;
    out[OFF_EMB + i] = w / g_newcs[i >> 6];
    if (i == 0) {
        double mse = g_mse / (double)NELEM;
        out[OFF_LOSS] = (float)(mse * 1.25 + g_entropy);
    }
}

// ---------------- launcher ---------------------------------------------------
extern "C" void kernel_launch(void* const* d_in, const int* in_sizes, int n_in,
                              void* d_out, int out_size) {
    const float* X   = (const float*)d_in[0];
    const float* E   = (const float*)d_in[1];
    const float* R   = (const float*)d_in[2];
    const float* CS  = (const float*)d_in[3];
    const float* EW  = (const float*)d_in[4];
    float* out = (float*)d_out;

    static bool attr_set = false;
    if (!attr_set) {
        cudaFuncSetAttribute(k_gemm, cudaFuncAttributeMaxDynamicSharedMemorySize, GEMM_SMEM);
        attr_set = true;
    }

    k_init<<<260, 256>>>(E);
    k_gemm<<<512, 256, GEMM_SMEM>>>(E, X, R, out + OFF_IDX);
    k_quant<<<1025, 256>>>(X, CS, out);     // block 1024 = hidden cs/entropy reduce
    k_ema<<<256, 256>>>(EW, out);           // block0/thread0 writes loss
}